// round 14
// baseline (speedup 1.0000x reference)
#include <cuda_runtime.h>
#include <math.h>

// Problem constants
#define B_  4
#define S_  2048
#define D_  1024
#define F_  4096
#define E_  8
#define T_  (B_*S_)          // 8192 tokens
#define NA_ (T_*2)           // 16384 assignments (top-2)

// GEMM tiling
#define BM 128
#define BN 64
#define BK 16
#define NTHREADS 256

// ---------------------------------------------------------------------------
// Scratch (device globals; no allocations anywhere)
// ---------------------------------------------------------------------------
__device__ int   g_count[E_];
__device__ float g_pacc[E_];
__device__ float g_zacc;
__device__ int   g_tok [E_*T_];
__device__ int   g_slot[E_*T_];
__device__ float g_gate[E_*T_];
__device__ float g_H[(size_t)NA_ * F_];   // SwiGLU hidden, 268 MB
__device__ float g_Y[(size_t)NA_ * D_];   // per-assignment down output, 67 MB

// ---------------------------------------------------------------------------
// 0) zero the per-launch accumulators (graph-replay safe)
// ---------------------------------------------------------------------------
__global__ void init_kernel() {
    int i = threadIdx.x;
    if (i < E_) { g_count[i] = 0; g_pacc[i] = 0.f; }
    if (i == 0) g_zacc = 0.f;
}

// ---------------------------------------------------------------------------
// 1) router: logits, softmax stats, top-2, gather lists
//    1 warp per token, 8 warps per block
// ---------------------------------------------------------------------------
__global__ void router_kernel(const float* __restrict__ x,
                              const float* __restrict__ Wr) {
    int warp = threadIdx.x >> 5;
    int lane = threadIdx.x & 31;
    int t = blockIdx.x * 8 + warp;
    if (t >= T_) return;

    const float* xr = x + (size_t)t * D_;
    float acc[E_];
#pragma unroll
    for (int e = 0; e < E_; e++) acc[e] = 0.f;

    for (int d = lane; d < D_; d += 32) {
        float xv = xr[d];
        const float* w = Wr + d * E_;
#pragma unroll
        for (int e = 0; e < E_; e++) acc[e] += xv * w[e];
    }
#pragma unroll
    for (int off = 16; off; off >>= 1) {
#pragma unroll
        for (int e = 0; e < E_; e++)
            acc[e] += __shfl_xor_sync(0xffffffffu, acc[e], off);
    }

    if (lane == 0) {
        // softmax stats + z-loss
        float mx = acc[0];
#pragma unroll
        for (int e = 1; e < E_; e++) mx = fmaxf(mx, acc[e]);
        float ex[E_], s = 0.f;
#pragma unroll
        for (int e = 0; e < E_; e++) { ex[e] = expf(acc[e] - mx); s += ex[e]; }
        float lse = mx + logf(s);
        atomicAdd(&g_zacc, lse * lse);
        float inv = 1.f / s;
#pragma unroll
        for (int e = 0; e < E_; e++) atomicAdd(&g_pacc[e], ex[e] * inv);

        // top-2 (strict > keeps lowest index on tie, matching lax.top_k)
        int i0 = 0;
#pragma unroll
        for (int e = 1; e < E_; e++) if (acc[e] > acc[i0]) i0 = e;
        int i1 = (i0 == 0) ? 1 : 0;
#pragma unroll
        for (int e = 0; e < E_; e++)
            if (e != i0 && acc[e] > acc[i1]) i1 = e;

        // softmax over the two top logits
        float g0 = 1.f / (1.f + expf(acc[i1] - acc[i0]));
        float g1 = 1.f - g0;

        int p0 = atomicAdd(&g_count[i0], 1);
        g_tok [i0*T_ + p0] = t;
        g_slot[i0*T_ + p0] = 2*t;
        g_gate[i0*T_ + p0] = g0;
        int p1 = atomicAdd(&g_count[i1], 1);
        g_tok [i1*T_ + p1] = t;
        g_slot[i1*T_ + p1] = 2*t + 1;
        g_gate[i1*T_ + p1] = g1;
    }
}

// ---------------------------------------------------------------------------
// 2) up+gate fused GEMM with gathered A rows, SiLU*gate epilogue -> g_H
//    C[i,n] = silu(Xg @ Wup[e])[i,n] * (Xg @ Wgate[e])[i,n]
// ---------------------------------------------------------------------------
__global__ void __launch_bounds__(NTHREADS, 2)
upgate_kernel(const float* __restrict__ x,
              const float* __restrict__ Wup,
              const float* __restrict__ Wgate) {
    const int e  = blockIdx.z;
    const int ne = g_count[e];
    const int m0 = blockIdx.y * BM;
    if (m0 >= ne) return;
    const int n0 = blockIdx.x * BN;

    const float* Bu = Wup   + (size_t)e * D_ * F_;
    const float* Bg = Wgate + (size_t)e * D_ * F_;

    __shared__ __align__(16) float As [BK][BM];
    __shared__ __align__(16) float BsU[BK][BN];
    __shared__ __align__(16) float BsG[BK][BN];

    const int tid = threadIdx.x;

    // A-tile load mapping: 512 float4 slots, 2 per thread
    const float* aptr[2];
    int arow[2], ac4[2];
#pragma unroll
    for (int i = 0; i < 2; i++) {
        int slot = tid + NTHREADS * i;
        int row  = slot >> 2;
        int c4   = slot & 3;
        arow[i] = row; ac4[i] = c4;
        int gr = m0 + row;
        if (gr < ne) {
            int tok = g_tok[e*T_ + gr];
            aptr[i] = x + (size_t)tok * D_ + c4 * 4;
        } else {
            aptr[i] = nullptr;
        }
    }
    // B-tile load mapping: 16x64 floats = 256 float4, 1 per thread per matrix
    const int brow = tid >> 4;     // 0..15 (k)
    const int bc4  = tid & 15;     // 0..15 (n/4)
    const float* bup = Bu + (size_t)brow * F_ + n0 + bc4 * 4;
    const float* bgp = Bg + (size_t)brow * F_ + n0 + bc4 * 4;

    const int tx = tid & 15;       // n micro (x4)
    const int ty = tid >> 4;       // m micro (x8)

    float accU[8][4], accG[8][4];
#pragma unroll
    for (int j = 0; j < 8; j++)
#pragma unroll
        for (int jj = 0; jj < 4; jj++) { accU[j][jj] = 0.f; accG[j][jj] = 0.f; }

    float4 ra[2], rbu, rbg;
    const float4 zero4 = make_float4(0.f, 0.f, 0.f, 0.f);

    // prefetch k-tile 0
#pragma unroll
    for (int i = 0; i < 2; i++)
        ra[i] = aptr[i] ? *(const float4*)(aptr[i]) : zero4;
    rbu = *(const float4*)(bup);
    rbg = *(const float4*)(bgp);

    const int NK = D_ / BK;  // 64
    for (int kt = 0; kt < NK; kt++) {
        __syncthreads();
#pragma unroll
        for (int i = 0; i < 2; i++) {
            As[ac4[i]*4 + 0][arow[i]] = ra[i].x;
            As[ac4[i]*4 + 1][arow[i]] = ra[i].y;
            As[ac4[i]*4 + 2][arow[i]] = ra[i].z;
            As[ac4[i]*4 + 3][arow[i]] = ra[i].w;
        }
        *(float4*)&BsU[brow][bc4*4] = rbu;
        *(float4*)&BsG[brow][bc4*4] = rbg;
        __syncthreads();

        if (kt + 1 < NK) {
            int k0 = (kt + 1) * BK;
#pragma unroll
            for (int i = 0; i < 2; i++)
                ra[i] = aptr[i] ? *(const float4*)(aptr[i] + k0) : zero4;
            rbu = *(const float4*)(bup + (size_t)k0 * F_);
            rbg = *(const float4*)(bgp + (size_t)k0 * F_);
        }

#pragma unroll
        for (int kk = 0; kk < BK; kk++) {
            float a[8];
#pragma unroll
            for (int j = 0; j < 8; j++) a[j] = As[kk][ty*8 + j];
            float4 bu = *(float4*)&BsU[kk][tx*4];
            float4 bg = *(float4*)&BsG[kk][tx*4];
#pragma unroll
            for (int j = 0; j < 8; j++) {
                accU[j][0] += a[j] * bu.x;  accU[j][1] += a[j] * bu.y;
                accU[j][2] += a[j] * bu.z;  accU[j][3] += a[j] * bu.w;
                accG[j][0] += a[j] * bg.x;  accG[j][1] += a[j] * bg.y;
                accG[j][2] += a[j] * bg.z;  accG[j][3] += a[j] * bg.w;
            }
        }
    }

    // epilogue: h = silu(u) * g  -> g_H[slot, n]
#pragma unroll
    for (int j = 0; j < 8; j++) {
        int row = m0 + ty*8 + j;
        if (row < ne) {
            int slot = g_slot[e*T_ + row];
            float* hrow = g_H + (size_t)slot * F_ + n0 + tx*4;
#pragma unroll
            for (int jj = 0; jj < 4; jj++) {
                float u = accU[j][jj];
                float g = accG[j][jj];
                hrow[jj] = (u / (1.f + expf(-u))) * g;
            }
        }
    }
}

// ---------------------------------------------------------------------------
// 3) down GEMM with gathered H rows, gate-scaled epilogue -> g_Y
// ---------------------------------------------------------------------------
__global__ void __launch_bounds__(NTHREADS, 2)
down_kernel(const float* __restrict__ Wdown) {
    const int e  = blockIdx.z;
    const int ne = g_count[e];
    const int m0 = blockIdx.y * BM;
    if (m0 >= ne) return;
    const int n0 = blockIdx.x * BN;

    const float* Bd = Wdown + (size_t)e * F_ * D_;

    __shared__ __align__(16) float As[BK][BM];
    __shared__ __align__(16) float Bs[BK][BN];

    const int tid = threadIdx.x;

    const float* aptr[2];
    int arow[2], ac4[2];
#pragma unroll
    for (int i = 0; i < 2; i++) {
        int slot = tid + NTHREADS * i;
        int row  = slot >> 2;
        int c4   = slot & 3;
        arow[i] = row; ac4[i] = c4;
        int gr = m0 + row;
        if (gr < ne) {
            int hs = g_slot[e*T_ + gr];
            aptr[i] = g_H + (size_t)hs * F_ + c4 * 4;
        } else {
            aptr[i] = nullptr;
        }
    }
    const int brow = tid >> 4;
    const int bc4  = tid & 15;
    const float* bdp = Bd + (size_t)brow * D_ + n0 + bc4 * 4;

    const int tx = tid & 15;
    const int ty = tid >> 4;

    float acc[8][4];
#pragma unroll
    for (int j = 0; j < 8; j++)
#pragma unroll
        for (int jj = 0; jj < 4; jj++) acc[j][jj] = 0.f;

    float4 ra[2], rb;
    const float4 zero4 = make_float4(0.f, 0.f, 0.f, 0.f);

#pragma unroll
    for (int i = 0; i < 2; i++)
        ra[i] = aptr[i] ? *(const float4*)(aptr[i]) : zero4;
    rb = *(const float4*)(bdp);

    const int NK = F_ / BK;  // 256
    for (int kt = 0; kt < NK; kt++) {
        __syncthreads();
#pragma unroll
        for (int i = 0; i < 2; i++) {
            As[ac4[i]*4 + 0][arow[i]] = ra[i].x;
            As[ac4[i]*4 + 1][arow[i]] = ra[i].y;
            As[ac4[i]*4 + 2][arow[i]] = ra[i].z;
            As[ac4[i]*4 + 3][arow[i]] = ra[i].w;
        }
        *(float4*)&Bs[brow][bc4*4] = rb;
        __syncthreads();

        if (kt + 1 < NK) {
            int k0 = (kt + 1) * BK;
#pragma unroll
            for (int i = 0; i < 2; i++)
                ra[i] = aptr[i] ? *(const float4*)(aptr[i] + k0) : zero4;
            rb = *(const float4*)(bdp + (size_t)k0 * D_);
        }

#pragma unroll
        for (int kk = 0; kk < BK; kk++) {
            float a[8];
#pragma unroll
            for (int j = 0; j < 8; j++) a[j] = As[kk][ty*8 + j];
            float4 b = *(float4*)&Bs[kk][tx*4];
#pragma unroll
            for (int j = 0; j < 8; j++) {
                acc[j][0] += a[j] * b.x;  acc[j][1] += a[j] * b.y;
                acc[j][2] += a[j] * b.z;  acc[j][3] += a[j] * b.w;
            }
        }
    }

#pragma unroll
    for (int j = 0; j < 8; j++) {
        int row = m0 + ty*8 + j;
        if (row < ne) {
            int   slot = g_slot[e*T_ + row];
            float gate = g_gate[e*T_ + row];
            float* yrow = g_Y + (size_t)slot * D_ + n0 + tx*4;
#pragma unroll
            for (int jj = 0; jj < 4; jj++)
                yrow[jj] = acc[j][jj] * gate;
        }
    }
}

// ---------------------------------------------------------------------------
// 4) combine the two assignment slots per token -> output
// ---------------------------------------------------------------------------
__global__ void combine_kernel(float* __restrict__ out) {
    int t = blockIdx.x;
    int d = threadIdx.x * 4;
    float4 a = *(const float4*)(g_Y + (size_t)(2*t)     * D_ + d);
    float4 b = *(const float4*)(g_Y + (size_t)(2*t + 1) * D_ + d);
    float4 r = make_float4(a.x + b.x, a.y + b.y, a.z + b.z, a.w + b.w);
    *(float4*)(out + (size_t)t * D_ + d) = r;
}

// ---------------------------------------------------------------------------
// 5) losses + tokens_per_expert into the output tail
// ---------------------------------------------------------------------------
__global__ void finalize_kernel(float* __restrict__ out) {
    int tid = threadIdx.x;
    const float Tf = (float)T_;
    float* tail = out + (size_t)T_ * D_;
    if (tid < E_)
        tail[tid] = (float)g_count[tid] / (Tf * 2.f);
    if (tid == 0) {
        float z = g_zacc / Tf;
        float lb = 0.f;
#pragma unroll
        for (int e = 0; e < E_; e++)
            lb += (g_pacc[e] / Tf) * ((float)g_count[e] / (Tf * 2.f));
        lb *= (float)E_;
        float* s = tail + E_;
        s[0] = z;
        s[1] = z * 0.001f;
        s[2] = lb;
        s[3] = lb * 0.1f;
    }
}

// ---------------------------------------------------------------------------
// launch
// ---------------------------------------------------------------------------
extern "C" void kernel_launch(void* const* d_in, const int* in_sizes, int n_in,
                              void* d_out, int out_size) {
    (void)in_sizes; (void)n_in; (void)out_size;
    const float* x     = (const float*)d_in[0];
    const float* Wr    = (const float*)d_in[1];
    const float* Wup   = (const float*)d_in[2];
    const float* Wgate = (const float*)d_in[3];
    const float* Wdown = (const float*)d_in[4];
    float* out = (float*)d_out;

    init_kernel<<<1, 32>>>();
    router_kernel<<<T_ / 8, 256>>>(x, Wr);
    upgate_kernel<<<dim3(F_ / BN, T_ / BM, E_), NTHREADS>>>(x, Wup, Wgate);
    down_kernel<<<dim3(D_ / BN, T_ / BM, E_), NTHREADS>>>(Wdown);
    combine_kernel<<<T_, 256>>>(out);
    finalize_kernel<<<1, 32>>>(out);
}

// round 15
// speedup vs baseline: 1.0549x; 1.0549x over previous
#include <cuda_runtime.h>
#include <math.h>

// Problem constants
#define B_  4
#define S_  2048
#define D_  1024
#define F_  4096
#define E_  8
#define T_  (B_*S_)          // 8192 tokens
#define NA_ (T_*2)           // 16384 assignments (top-2)

// GEMM tiling
#define BM 128
#define BN 64
#define BK 16
#define NTHREADS 256

// ---------------------------------------------------------------------------
// Scratch (device globals; no allocations anywhere)
// ---------------------------------------------------------------------------
__device__ int   g_count[E_];
__device__ float g_pacc[E_];
__device__ float g_zacc;
__device__ int   g_tok [E_*T_];
__device__ int   g_slot[E_*T_];
__device__ float g_gate[E_*T_];
__device__ float g_H[(size_t)NA_ * F_];   // SwiGLU hidden, 268 MB
__device__ float g_Y[(size_t)NA_ * D_];   // per-assignment down output, 67 MB

// ---------------------------------------------------------------------------
// 0) zero the per-launch accumulators (graph-replay safe)
// ---------------------------------------------------------------------------
__global__ void init_kernel() {
    int i = threadIdx.x;
    if (i < E_) { g_count[i] = 0; g_pacc[i] = 0.f; }
    if (i == 0) g_zacc = 0.f;
}

// ---------------------------------------------------------------------------
// 1) router: logits, softmax stats, top-2, gather lists
//    1 warp per token, 8 warps per block
// ---------------------------------------------------------------------------
__global__ void router_kernel(const float* __restrict__ x,
                              const float* __restrict__ Wr) {
    int warp = threadIdx.x >> 5;
    int lane = threadIdx.x & 31;
    int t = blockIdx.x * 8 + warp;
    if (t >= T_) return;

    const float* xr = x + (size_t)t * D_;
    float acc[E_];
#pragma unroll
    for (int e = 0; e < E_; e++) acc[e] = 0.f;

    for (int d = lane; d < D_; d += 32) {
        float xv = xr[d];
        const float* w = Wr + d * E_;
#pragma unroll
        for (int e = 0; e < E_; e++) acc[e] += xv * w[e];
    }
#pragma unroll
    for (int off = 16; off; off >>= 1) {
#pragma unroll
        for (int e = 0; e < E_; e++)
            acc[e] += __shfl_xor_sync(0xffffffffu, acc[e], off);
    }

    if (lane == 0) {
        // softmax stats + z-loss
        float mx = acc[0];
#pragma unroll
        for (int e = 1; e < E_; e++) mx = fmaxf(mx, acc[e]);
        float ex[E_], s = 0.f;
#pragma unroll
        for (int e = 0; e < E_; e++) { ex[e] = expf(acc[e] - mx); s += ex[e]; }
        float lse = mx + logf(s);
        atomicAdd(&g_zacc, lse * lse);
        float inv = 1.f / s;
#pragma unroll
        for (int e = 0; e < E_; e++) atomicAdd(&g_pacc[e], ex[e] * inv);

        // top-2 (strict > keeps lowest index on tie, matching lax.top_k)
        int i0 = 0;
#pragma unroll
        for (int e = 1; e < E_; e++) if (acc[e] > acc[i0]) i0 = e;
        int i1 = (i0 == 0) ? 1 : 0;
#pragma unroll
        for (int e = 0; e < E_; e++)
            if (e != i0 && acc[e] > acc[i1]) i1 = e;

        // softmax over the two top logits
        float g0 = 1.f / (1.f + expf(acc[i1] - acc[i0]));
        float g1 = 1.f - g0;

        int p0 = atomicAdd(&g_count[i0], 1);
        g_tok [i0*T_ + p0] = t;
        g_slot[i0*T_ + p0] = 2*t;
        g_gate[i0*T_ + p0] = g0;
        int p1 = atomicAdd(&g_count[i1], 1);
        g_tok [i1*T_ + p1] = t;
        g_slot[i1*T_ + p1] = 2*t + 1;
        g_gate[i1*T_ + p1] = g1;
    }
}

// ---------------------------------------------------------------------------
// 2) up+gate fused GEMM with gathered A rows, SiLU*gate epilogue -> g_H
//    C[i,n] = silu(Xg @ Wup[e])[i,n] * (Xg @ Wgate[e])[i,n]
// ---------------------------------------------------------------------------
__global__ void __launch_bounds__(NTHREADS, 2)
upgate_kernel(const float* __restrict__ x,
              const float* __restrict__ Wup,
              const float* __restrict__ Wgate) {
    const int e  = blockIdx.z;
    const int ne = g_count[e];
    const int m0 = blockIdx.y * BM;
    if (m0 >= ne) return;
    const int n0 = blockIdx.x * BN;

    const float* Bu = Wup   + (size_t)e * D_ * F_;
    const float* Bg = Wgate + (size_t)e * D_ * F_;

    __shared__ __align__(16) float As [BK][BM];
    __shared__ __align__(16) float BsU[BK][BN];
    __shared__ __align__(16) float BsG[BK][BN];

    const int tid = threadIdx.x;

    // A-tile load mapping: 512 float4 slots, 2 per thread
    const float* aptr[2];
    int arow[2], ac4[2];
#pragma unroll
    for (int i = 0; i < 2; i++) {
        int slot = tid + NTHREADS * i;
        int row  = slot >> 2;
        int c4   = slot & 3;
        arow[i] = row; ac4[i] = c4;
        int gr = m0 + row;
        if (gr < ne) {
            int tok = g_tok[e*T_ + gr];
            aptr[i] = x + (size_t)tok * D_ + c4 * 4;
        } else {
            aptr[i] = nullptr;
        }
    }
    // B-tile load mapping: 16x64 floats = 256 float4, 1 per thread per matrix
    const int brow = tid >> 4;     // 0..15 (k)
    const int bc4  = tid & 15;     // 0..15 (n/4)
    const float* bup = Bu + (size_t)brow * F_ + n0 + bc4 * 4;
    const float* bgp = Bg + (size_t)brow * F_ + n0 + bc4 * 4;

    const int tx = tid & 15;       // n micro (x4)
    const int ty = tid >> 4;       // m micro (x8)

    float accU[8][4], accG[8][4];
#pragma unroll
    for (int j = 0; j < 8; j++)
#pragma unroll
        for (int jj = 0; jj < 4; jj++) { accU[j][jj] = 0.f; accG[j][jj] = 0.f; }

    float4 ra[2], rbu, rbg;
    const float4 zero4 = make_float4(0.f, 0.f, 0.f, 0.f);

    // prefetch k-tile 0
#pragma unroll
    for (int i = 0; i < 2; i++)
        ra[i] = aptr[i] ? *(const float4*)(aptr[i]) : zero4;
    rbu = *(const float4*)(bup);
    rbg = *(const float4*)(bgp);

    const int NK = D_ / BK;  // 64
    for (int kt = 0; kt < NK; kt++) {
        __syncthreads();
#pragma unroll
        for (int i = 0; i < 2; i++) {
            As[ac4[i]*4 + 0][arow[i]] = ra[i].x;
            As[ac4[i]*4 + 1][arow[i]] = ra[i].y;
            As[ac4[i]*4 + 2][arow[i]] = ra[i].z;
            As[ac4[i]*4 + 3][arow[i]] = ra[i].w;
        }
        *(float4*)&BsU[brow][bc4*4] = rbu;
        *(float4*)&BsG[brow][bc4*4] = rbg;
        __syncthreads();

        if (kt + 1 < NK) {
            int k0 = (kt + 1) * BK;
#pragma unroll
            for (int i = 0; i < 2; i++)
                ra[i] = aptr[i] ? *(const float4*)(aptr[i] + k0) : zero4;
            rbu = *(const float4*)(bup + (size_t)k0 * F_);
            rbg = *(const float4*)(bgp + (size_t)k0 * F_);
        }

#pragma unroll
        for (int kk = 0; kk < BK; kk++) {
            float a[8];
#pragma unroll
            for (int j = 0; j < 8; j++) a[j] = As[kk][ty*8 + j];
            float4 bu = *(float4*)&BsU[kk][tx*4];
            float4 bg = *(float4*)&BsG[kk][tx*4];
#pragma unroll
            for (int j = 0; j < 8; j++) {
                accU[j][0] += a[j] * bu.x;  accU[j][1] += a[j] * bu.y;
                accU[j][2] += a[j] * bu.z;  accU[j][3] += a[j] * bu.w;
                accG[j][0] += a[j] * bg.x;  accG[j][1] += a[j] * bg.y;
                accG[j][2] += a[j] * bg.z;  accG[j][3] += a[j] * bg.w;
            }
        }
    }

    // epilogue: h = silu(u) * g  -> g_H[slot, n]
#pragma unroll
    for (int j = 0; j < 8; j++) {
        int row = m0 + ty*8 + j;
        if (row < ne) {
            int slot = g_slot[e*T_ + row];
            float* hrow = g_H + (size_t)slot * F_ + n0 + tx*4;
#pragma unroll
            for (int jj = 0; jj < 4; jj++) {
                float u = accU[j][jj];
                float g = accG[j][jj];
                hrow[jj] = (u / (1.f + expf(-u))) * g;
            }
        }
    }
}

// ---------------------------------------------------------------------------
// 3) down GEMM with gathered H rows, gate-scaled epilogue -> g_Y
// ---------------------------------------------------------------------------
__global__ void __launch_bounds__(NTHREADS, 2)
down_kernel(const float* __restrict__ Wdown) {
    const int e  = blockIdx.z;
    const int ne = g_count[e];
    const int m0 = blockIdx.y * BM;
    if (m0 >= ne) return;
    const int n0 = blockIdx.x * BN;

    const float* Bd = Wdown + (size_t)e * F_ * D_;

    __shared__ __align__(16) float As[BK][BM];
    __shared__ __align__(16) float Bs[BK][BN];

    const int tid = threadIdx.x;

    const float* aptr[2];
    int arow[2], ac4[2];
#pragma unroll
    for (int i = 0; i < 2; i++) {
        int slot = tid + NTHREADS * i;
        int row  = slot >> 2;
        int c4   = slot & 3;
        arow[i] = row; ac4[i] = c4;
        int gr = m0 + row;
        if (gr < ne) {
            int hs = g_slot[e*T_ + gr];
            aptr[i] = g_H + (size_t)hs * F_ + c4 * 4;
        } else {
            aptr[i] = nullptr;
        }
    }
    const int brow = tid >> 4;
    const int bc4  = tid & 15;
    const float* bdp = Bd + (size_t)brow * D_ + n0 + bc4 * 4;

    const int tx = tid & 15;
    const int ty = tid >> 4;

    float acc[8][4];
#pragma unroll
    for (int j = 0; j < 8; j++)
#pragma unroll
        for (int jj = 0; jj < 4; jj++) acc[j][jj] = 0.f;

    float4 ra[2], rb;
    const float4 zero4 = make_float4(0.f, 0.f, 0.f, 0.f);

#pragma unroll
    for (int i = 0; i < 2; i++)
        ra[i] = aptr[i] ? *(const float4*)(aptr[i]) : zero4;
    rb = *(const float4*)(bdp);

    const int NK = F_ / BK;  // 256
    for (int kt = 0; kt < NK; kt++) {
        __syncthreads();
#pragma unroll
        for (int i = 0; i < 2; i++) {
            As[ac4[i]*4 + 0][arow[i]] = ra[i].x;
            As[ac4[i]*4 + 1][arow[i]] = ra[i].y;
            As[ac4[i]*4 + 2][arow[i]] = ra[i].z;
            As[ac4[i]*4 + 3][arow[i]] = ra[i].w;
        }
        *(float4*)&Bs[brow][bc4*4] = rb;
        __syncthreads();

        if (kt + 1 < NK) {
            int k0 = (kt + 1) * BK;
#pragma unroll
            for (int i = 0; i < 2; i++)
                ra[i] = aptr[i] ? *(const float4*)(aptr[i] + k0) : zero4;
            rb = *(const float4*)(bdp + (size_t)k0 * D_);
        }

#pragma unroll
        for (int kk = 0; kk < BK; kk++) {
            float a[8];
#pragma unroll
            for (int j = 0; j < 8; j++) a[j] = As[kk][ty*8 + j];
            float4 b = *(float4*)&Bs[kk][tx*4];
#pragma unroll
            for (int j = 0; j < 8; j++) {
                acc[j][0] += a[j] * b.x;  acc[j][1] += a[j] * b.y;
                acc[j][2] += a[j] * b.z;  acc[j][3] += a[j] * b.w;
            }
        }
    }

#pragma unroll
    for (int j = 0; j < 8; j++) {
        int row = m0 + ty*8 + j;
        if (row < ne) {
            int   slot = g_slot[e*T_ + row];
            float gate = g_gate[e*T_ + row];
            float* yrow = g_Y + (size_t)slot * D_ + n0 + tx*4;
#pragma unroll
            for (int jj = 0; jj < 4; jj++)
                yrow[jj] = acc[j][jj] * gate;
        }
    }
}

// ---------------------------------------------------------------------------
// 4) combine the two assignment slots per token -> output
// ---------------------------------------------------------------------------
__global__ void combine_kernel(float* __restrict__ out) {
    int t = blockIdx.x;
    int d = threadIdx.x * 4;
    float4 a = *(const float4*)(g_Y + (size_t)(2*t)     * D_ + d);
    float4 b = *(const float4*)(g_Y + (size_t)(2*t + 1) * D_ + d);
    float4 r = make_float4(a.x + b.x, a.y + b.y, a.z + b.z, a.w + b.w);
    *(float4*)(out + (size_t)t * D_ + d) = r;
}

// ---------------------------------------------------------------------------
// 5) losses + tokens_per_expert into the output tail
// ---------------------------------------------------------------------------
__global__ void finalize_kernel(float* __restrict__ out) {
    int tid = threadIdx.x;
    const float Tf = (float)T_;
    float* tail = out + (size_t)T_ * D_;
    if (tid < E_)
        tail[tid] = (float)g_count[tid] / (Tf * 2.f);
    if (tid == 0) {
        float z = g_zacc / Tf;
        float lb = 0.f;
#pragma unroll
        for (int e = 0; e < E_; e++)
            lb += (g_pacc[e] / Tf) * ((float)g_count[e] / (Tf * 2.f));
        lb *= (float)E_;
        float* s = tail + E_;
        s[0] = z;
        s[1] = z * 0.001f;
        s[2] = lb;
        s[3] = lb * 0.1f;
    }
}

// ---------------------------------------------------------------------------
// launch
// ---------------------------------------------------------------------------
extern "C" void kernel_launch(void* const* d_in, const int* in_sizes, int n_in,
                              void* d_out, int out_size) {
    (void)in_sizes; (void)n_in; (void)out_size;
    const float* x     = (const float*)d_in[0];
    const float* Wr    = (const float*)d_in[1];
    const float* Wup   = (const float*)d_in[2];
    const float* Wgate = (const float*)d_in[3];
    const float* Wdown = (const float*)d_in[4];
    float* out = (float*)d_out;

    init_kernel<<<1, 32>>>();
    router_kernel<<<T_ / 8, 256>>>(x, Wr);
    upgate_kernel<<<dim3(F_ / BN, T_ / BM, E_), NTHREADS>>>(x, Wup, Wgate);
    down_kernel<<<dim3(D_ / BN, T_ / BM, E_), NTHREADS>>>(Wdown);
    combine_kernel<<<T_, 256>>>(out);
    finalize_kernel<<<1, 32>>>(out);
}

// round 17
// speedup vs baseline: 2.0063x; 1.9019x over previous
#include <cuda_runtime.h>
#include <cuda_bf16.h>
#include <math.h>

// Problem constants
#define B_  4
#define S_  2048
#define D_  1024
#define F_  4096
#define E_  8
#define T_  (B_*S_)          // 8192 tokens
#define NA_ (T_*2)           // 16384 assignments (top-2)

#define NSU (D_/32)          // 32 K-stages (upgate)
#define NSD (F_/32)          // 128 K-stages (down)
#define ASTR  40             // A smem stride in bf16 (conflict-free frag loads)
#define BSTRW 72             // B smem stride in 32-bit pair-words (conflict-free)

// ---------------------------------------------------------------------------
// Scratch (device globals; no allocations anywhere)
// ---------------------------------------------------------------------------
__device__ int   g_count[E_];
__device__ float g_pacc[E_];
__device__ float g_zacc;
__device__ int   g_tok [E_*T_];
__device__ int   g_slot[E_*T_];
__device__ float g_gate[E_*T_];
__device__ float g_H[(size_t)NA_ * F_];   // SwiGLU hidden, 268 MB
__device__ float g_Y[(size_t)NA_ * D_];   // per-assignment down output, 67 MB

// ---------------------------------------------------------------------------
// mma.sync m16n8k16 bf16 (baseline PTX, compute_80+ -> legacy HMMA on sm_103)
// ---------------------------------------------------------------------------
__device__ __forceinline__ void mma_bf16(float* c,
                                         unsigned a0, unsigned a1,
                                         unsigned a2, unsigned a3,
                                         unsigned b0, unsigned b1) {
    asm("mma.sync.aligned.m16n8k16.row.col.f32.bf16.bf16.f32 "
        "{%0,%1,%2,%3}, {%4,%5,%6,%7}, {%8,%9}, {%0,%1,%2,%3};"
        : "+f"(c[0]), "+f"(c[1]), "+f"(c[2]), "+f"(c[3])
        : "r"(a0), "r"(a1), "r"(a2), "r"(a3), "r"(b0), "r"(b1));
}

__device__ __forceinline__ void splitf(float v, __nv_bfloat16& h, __nv_bfloat16& l) {
    h = __float2bfloat16_rn(v);
    l = __float2bfloat16_rn(v - __bfloat162float(h));
}

// ---------------------------------------------------------------------------
// 0) zero the per-launch accumulators (graph-replay safe)
// ---------------------------------------------------------------------------
__global__ void init_kernel() {
    int i = threadIdx.x;
    if (i < E_) { g_count[i] = 0; g_pacc[i] = 0.f; }
    if (i == 0) g_zacc = 0.f;
}

// ---------------------------------------------------------------------------
// 1) router: logits, softmax stats, top-2, gather lists (verified correct)
// ---------------------------------------------------------------------------
__global__ void router_kernel(const float* __restrict__ x,
                              const float* __restrict__ Wr) {
    int warp = threadIdx.x >> 5;
    int lane = threadIdx.x & 31;
    int t = blockIdx.x * 8 + warp;
    if (t >= T_) return;

    const float* xr = x + (size_t)t * D_;
    float acc[E_];
#pragma unroll
    for (int e = 0; e < E_; e++) acc[e] = 0.f;
    for (int d = lane; d < D_; d += 32) {
        float xv = xr[d];
        const float* w = Wr + d * E_;
#pragma unroll
        for (int e = 0; e < E_; e++) acc[e] += xv * w[e];
    }
#pragma unroll
    for (int off = 16; off; off >>= 1) {
#pragma unroll
        for (int e = 0; e < E_; e++)
            acc[e] += __shfl_xor_sync(0xffffffffu, acc[e], off);
    }
    if (lane == 0) {
        float mx = acc[0];
#pragma unroll
        for (int e = 1; e < E_; e++) mx = fmaxf(mx, acc[e]);
        float ex[E_], s = 0.f;
#pragma unroll
        for (int e = 0; e < E_; e++) { ex[e] = expf(acc[e] - mx); s += ex[e]; }
        float lse = mx + logf(s);
        atomicAdd(&g_zacc, lse * lse);
        float inv = 1.f / s;
#pragma unroll
        for (int e = 0; e < E_; e++) atomicAdd(&g_pacc[e], ex[e] * inv);

        int i0 = 0;
#pragma unroll
        for (int e = 1; e < E_; e++) if (acc[e] > acc[i0]) i0 = e;
        int i1 = (i0 == 0) ? 1 : 0;
#pragma unroll
        for (int e = 0; e < E_; e++)
            if (e != i0 && acc[e] > acc[i1]) i1 = e;

        float g0 = 1.f / (1.f + expf(acc[i1] - acc[i0]));
        float g1 = 1.f - g0;

        int p0 = atomicAdd(&g_count[i0], 1);
        g_tok [i0*T_ + p0] = t;  g_slot[i0*T_ + p0] = 2*t;   g_gate[i0*T_ + p0] = g0;
        int p1 = atomicAdd(&g_count[i1], 1);
        g_tok [i1*T_ + p1] = t;  g_slot[i1*T_ + p1] = 2*t+1; g_gate[i1*T_ + p1] = g1;
    }
}

// ---------------------------------------------------------------------------
// 2) upgate: 3xBF16-split mma.sync GEMM (M=128, N=64 of U and G, K=1024),
//    gathered token rows, SiLU*gate epilogue -> g_H
//    8 warps: warp grid 4(m) x 2(n), warp tile 32x32 per matrix.
// ---------------------------------------------------------------------------
__global__ void __launch_bounds__(256)
upgate_mma(const float* __restrict__ x,
           const float* __restrict__ Wup,
           const float* __restrict__ Wgate) {
    __shared__ __nv_bfloat16 Ah[128*ASTR];
    __shared__ __nv_bfloat16 Al[128*ASTR];
    __shared__ unsigned BUh[16*BSTRW];
    __shared__ unsigned BUl[16*BSTRW];
    __shared__ unsigned BGh[16*BSTRW];
    __shared__ unsigned BGl[16*BSTRW];

    const int e  = blockIdx.z;
    const int ne = g_count[e];
    const int m0 = blockIdx.y * 128;
    if (m0 >= ne) return;
    const int n0 = blockIdx.x * 64;

    const int tid  = threadIdx.x;
    const int lane = tid & 31, wid = tid >> 5;
    const int grp  = lane >> 2, tig = lane & 3;
    const int wm   = wid >> 1,  wn  = wid & 1;

    const float* WuE = Wup   + (size_t)e * D_ * F_;
    const float* WgE = Wgate + (size_t)e * D_ * F_;

    // A loaders: 1024 float4 / 256 threads = 4 slots each
    const float* ap[4]; int arow[4], ac4[4];
#pragma unroll
    for (int i = 0; i < 4; i++) {
        int s = tid + 256*i;
        arow[i] = s >> 3; ac4[i] = s & 7;
        int gr = m0 + arow[i];
        ap[i] = (gr < ne) ? x + (size_t)g_tok[e*T_ + gr] * D_ + ac4[i]*4
                          : (const float*)0;
    }
    // B loaders: 512 float4 per matrix / 256 threads = 2 slots each
    int bk[2], bn4[2]; const float* bup[2]; const float* bgp[2];
#pragma unroll
    for (int i = 0; i < 2; i++) {
        int s = tid + 256*i;
        bk[i] = s >> 4; bn4[i] = s & 15;
        bup[i] = WuE + (size_t)bk[i]*F_ + n0 + bn4[i]*4;
        bgp[i] = WgE + (size_t)bk[i]*F_ + n0 + bn4[i]*4;
    }

    float accU[2][4][4], accG[2][4][4];
#pragma unroll
    for (int mf = 0; mf < 2; mf++)
#pragma unroll
        for (int nf = 0; nf < 4; nf++)
#pragma unroll
            for (int q = 0; q < 4; q++) { accU[mf][nf][q] = 0.f; accG[mf][nf][q] = 0.f; }

    const float4 z4 = make_float4(0.f, 0.f, 0.f, 0.f);
    float4 va[4], vu[2], vg[2];
#pragma unroll
    for (int i = 0; i < 4; i++) va[i] = ap[i] ? *(const float4*)ap[i] : z4;
#pragma unroll
    for (int i = 0; i < 2; i++) {
        vu[i] = *(const float4*)bup[i];
        vg[i] = *(const float4*)bgp[i];
    }

    for (int s = 0; s < NSU; s++) {
        __syncthreads();
        // ---- store stage into smem (fp32 -> bf16 hi/lo split) ----
#pragma unroll
        for (int i = 0; i < 4; i++) {
            __nv_bfloat16 h0,l0,h1,l1,h2,l2,h3,l3;
            splitf(va[i].x, h0, l0); splitf(va[i].y, h1, l1);
            splitf(va[i].z, h2, l2); splitf(va[i].w, h3, l3);
            int base = arow[i]*ASTR + ac4[i]*4;
            *(__nv_bfloat162*)&Ah[base]   = __halves2bfloat162(h0, h1);
            *(__nv_bfloat162*)&Ah[base+2] = __halves2bfloat162(h2, h3);
            *(__nv_bfloat162*)&Al[base]   = __halves2bfloat162(l0, l1);
            *(__nv_bfloat162*)&Al[base+2] = __halves2bfloat162(l2, l3);
        }
#pragma unroll
        for (int i = 0; i < 2; i++) {
            int kp = bk[i] >> 1, kb = bk[i] & 1;
            float fu[4] = {vu[i].x, vu[i].y, vu[i].z, vu[i].w};
            float fg[4] = {vg[i].x, vg[i].y, vg[i].z, vg[i].w};
#pragma unroll
            for (int j = 0; j < 4; j++) {
                int idx = (kp*BSTRW + bn4[i]*4 + j)*2 + kb;
                __nv_bfloat16 h, l;
                splitf(fu[j], h, l);
                ((__nv_bfloat16*)BUh)[idx] = h; ((__nv_bfloat16*)BUl)[idx] = l;
                splitf(fg[j], h, l);
                ((__nv_bfloat16*)BGh)[idx] = h; ((__nv_bfloat16*)BGl)[idx] = l;
            }
        }
        __syncthreads();
        // ---- prefetch next stage ----
        if (s + 1 < NSU) {
            int k0 = (s + 1) * 32;
#pragma unroll
            for (int i = 0; i < 4; i++) va[i] = ap[i] ? *(const float4*)(ap[i] + k0) : z4;
#pragma unroll
            for (int i = 0; i < 2; i++) {
                vu[i] = *(const float4*)(bup[i] + (size_t)k0*F_);
                vg[i] = *(const float4*)(bgp[i] + (size_t)k0*F_);
            }
        }
        // ---- compute 2 x k16 ----
#pragma unroll
        for (int kk2 = 0; kk2 < 2; kk2++) {
            unsigned ah[2][4], al[2][4];
#pragma unroll
            for (int mf = 0; mf < 2; mf++) {
                const __nv_bfloat16* Ab = Ah + (wm*32 + mf*16 + grp)*ASTR + kk2*16 + tig*2;
                ah[mf][0] = *(const unsigned*)(Ab);
                ah[mf][1] = *(const unsigned*)(Ab + 8*ASTR);
                ah[mf][2] = *(const unsigned*)(Ab + 8);
                ah[mf][3] = *(const unsigned*)(Ab + 8*ASTR + 8);
                const __nv_bfloat16* Abl = Al + (wm*32 + mf*16 + grp)*ASTR + kk2*16 + tig*2;
                al[mf][0] = *(const unsigned*)(Abl);
                al[mf][1] = *(const unsigned*)(Abl + 8*ASTR);
                al[mf][2] = *(const unsigned*)(Abl + 8);
                al[mf][3] = *(const unsigned*)(Abl + 8*ASTR + 8);
            }
            unsigned buh[4][2], bul[4][2], bgh[4][2], bgl[4][2];
#pragma unroll
            for (int nf = 0; nf < 4; nf++) {
                int nn = wn*32 + nf*8 + grp;
                int r0 = (kk2*8 + tig)*BSTRW + nn;
                int r1 = (kk2*8 + tig + 4)*BSTRW + nn;
                buh[nf][0] = BUh[r0]; buh[nf][1] = BUh[r1];
                bul[nf][0] = BUl[r0]; bul[nf][1] = BUl[r1];
                bgh[nf][0] = BGh[r0]; bgh[nf][1] = BGh[r1];
                bgl[nf][0] = BGl[r0]; bgl[nf][1] = BGl[r1];
            }
            // hi*hi
#pragma unroll
            for (int nf = 0; nf < 4; nf++)
#pragma unroll
                for (int mf = 0; mf < 2; mf++) {
                    mma_bf16(accU[mf][nf], ah[mf][0],ah[mf][1],ah[mf][2],ah[mf][3], buh[nf][0], buh[nf][1]);
                    mma_bf16(accG[mf][nf], ah[mf][0],ah[mf][1],ah[mf][2],ah[mf][3], bgh[nf][0], bgh[nf][1]);
                }
            // lo*hi
#pragma unroll
            for (int nf = 0; nf < 4; nf++)
#pragma unroll
                for (int mf = 0; mf < 2; mf++) {
                    mma_bf16(accU[mf][nf], al[mf][0],al[mf][1],al[mf][2],al[mf][3], buh[nf][0], buh[nf][1]);
                    mma_bf16(accG[mf][nf], al[mf][0],al[mf][1],al[mf][2],al[mf][3], bgh[nf][0], bgh[nf][1]);
                }
            // hi*lo
#pragma unroll
            for (int nf = 0; nf < 4; nf++)
#pragma unroll
                for (int mf = 0; mf < 2; mf++) {
                    mma_bf16(accU[mf][nf], ah[mf][0],ah[mf][1],ah[mf][2],ah[mf][3], bul[nf][0], bul[nf][1]);
                    mma_bf16(accG[mf][nf], ah[mf][0],ah[mf][1],ah[mf][2],ah[mf][3], bgl[nf][0], bgl[nf][1]);
                }
        }
    }

    // ---- epilogue: h = silu(u)*g -> g_H[slot, n] ----
#pragma unroll
    for (int mf = 0; mf < 2; mf++) {
#pragma unroll
        for (int h = 0; h < 2; h++) {
            int r  = wm*32 + mf*16 + grp + h*8;
            int gr = m0 + r;
            if (gr < ne) {
                int slot = g_slot[e*T_ + gr];
                float* hrow = g_H + (size_t)slot * F_ + n0 + wn*32 + tig*2;
#pragma unroll
                for (int nf = 0; nf < 4; nf++) {
                    float u0 = accU[mf][nf][h*2+0], g0 = accG[mf][nf][h*2+0];
                    float u1 = accU[mf][nf][h*2+1], g1 = accG[mf][nf][h*2+1];
                    float o0 = (u0 / (1.f + expf(-u0))) * g0;
                    float o1 = (u1 / (1.f + expf(-u1))) * g1;
                    *(float2*)(hrow + nf*8) = make_float2(o0, o1);
                }
            }
        }
    }
}

// ---------------------------------------------------------------------------
// 3) down: 3xBF16-split mma.sync GEMM (M=128, N=64, K=4096),
//    gathered H rows, gate-scaled epilogue -> g_Y
// ---------------------------------------------------------------------------
__global__ void __launch_bounds__(256)
down_mma(const float* __restrict__ Wdown) {
    __shared__ __nv_bfloat16 Ah[128*ASTR];
    __shared__ __nv_bfloat16 Al[128*ASTR];
    __shared__ unsigned Bh[16*BSTRW];
    __shared__ unsigned Bl[16*BSTRW];

    const int e  = blockIdx.z;
    const int ne = g_count[e];
    const int m0 = blockIdx.y * 128;
    if (m0 >= ne) return;
    const int n0 = blockIdx.x * 64;

    const int tid  = threadIdx.x;
    const int lane = tid & 31, wid = tid >> 5;
    const int grp  = lane >> 2, tig = lane & 3;
    const int wm   = wid >> 1,  wn  = wid & 1;

    const float* WdE = Wdown + (size_t)e * F_ * D_;

    const float* ap[4]; int arow[4], ac4[4];
#pragma unroll
    for (int i = 0; i < 4; i++) {
        int s = tid + 256*i;
        arow[i] = s >> 3; ac4[i] = s & 7;
        int gr = m0 + arow[i];
        ap[i] = (gr < ne) ? g_H + (size_t)g_slot[e*T_ + gr] * F_ + ac4[i]*4
                          : (const float*)0;
    }
    int bk[2], bn4[2]; const float* bp[2];
#pragma unroll
    for (int i = 0; i < 2; i++) {
        int s = tid + 256*i;
        bk[i] = s >> 4; bn4[i] = s & 15;
        bp[i] = WdE + (size_t)bk[i]*D_ + n0 + bn4[i]*4;
    }

    float acc[2][4][4];
#pragma unroll
    for (int mf = 0; mf < 2; mf++)
#pragma unroll
        for (int nf = 0; nf < 4; nf++)
#pragma unroll
            for (int q = 0; q < 4; q++) acc[mf][nf][q] = 0.f;

    const float4 z4 = make_float4(0.f, 0.f, 0.f, 0.f);
    float4 va[4], vb[2];
#pragma unroll
    for (int i = 0; i < 4; i++) va[i] = ap[i] ? *(const float4*)ap[i] : z4;
#pragma unroll
    for (int i = 0; i < 2; i++) vb[i] = *(const float4*)bp[i];

    for (int s = 0; s < NSD; s++) {
        __syncthreads();
#pragma unroll
        for (int i = 0; i < 4; i++) {
            __nv_bfloat16 h0,l0,h1,l1,h2,l2,h3,l3;
            splitf(va[i].x, h0, l0); splitf(va[i].y, h1, l1);
            splitf(va[i].z, h2, l2); splitf(va[i].w, h3, l3);
            int base = arow[i]*ASTR + ac4[i]*4;
            *(__nv_bfloat162*)&Ah[base]   = __halves2bfloat162(h0, h1);
            *(__nv_bfloat162*)&Ah[base+2] = __halves2bfloat162(h2, h3);
            *(__nv_bfloat162*)&Al[base]   = __halves2bfloat162(l0, l1);
            *(__nv_bfloat162*)&Al[base+2] = __halves2bfloat162(l2, l3);
        }
#pragma unroll
        for (int i = 0; i < 2; i++) {
            int kp = bk[i] >> 1, kb = bk[i] & 1;
            float fb[4] = {vb[i].x, vb[i].y, vb[i].z, vb[i].w};
#pragma unroll
            for (int j = 0; j < 4; j++) {
                int idx = (kp*BSTRW + bn4[i]*4 + j)*2 + kb;
                __nv_bfloat16 h, l;
                splitf(fb[j], h, l);
                ((__nv_bfloat16*)Bh)[idx] = h; ((__nv_bfloat16*)Bl)[idx] = l;
            }
        }
        __syncthreads();
        if (s + 1 < NSD) {
            int k0 = (s + 1) * 32;
#pragma unroll
            for (int i = 0; i < 4; i++) va[i] = ap[i] ? *(const float4*)(ap[i] + k0) : z4;
#pragma unroll
            for (int i = 0; i < 2; i++) vb[i] = *(const float4*)(bp[i] + (size_t)k0*D_);
        }
#pragma unroll
        for (int kk2 = 0; kk2 < 2; kk2++) {
            unsigned ah[2][4], al[2][4];
#pragma unroll
            for (int mf = 0; mf < 2; mf++) {
                const __nv_bfloat16* Ab = Ah + (wm*32 + mf*16 + grp)*ASTR + kk2*16 + tig*2;
                ah[mf][0] = *(const unsigned*)(Ab);
                ah[mf][1] = *(const unsigned*)(Ab + 8*ASTR);
                ah[mf][2] = *(const unsigned*)(Ab + 8);
                ah[mf][3] = *(const unsigned*)(Ab + 8*ASTR + 8);
                const __nv_bfloat16* Abl = Al + (wm*32 + mf*16 + grp)*ASTR + kk2*16 + tig*2;
                al[mf][0] = *(const unsigned*)(Abl);
                al[mf][1] = *(const unsigned*)(Abl + 8*ASTR);
                al[mf][2] = *(const unsigned*)(Abl + 8);
                al[mf][3] = *(const unsigned*)(Abl + 8*ASTR + 8);
            }
            unsigned bh[4][2], bl[4][2];
#pragma unroll
            for (int nf = 0; nf < 4; nf++) {
                int nn = wn*32 + nf*8 + grp;
                int r0 = (kk2*8 + tig)*BSTRW + nn;
                int r1 = (kk2*8 + tig + 4)*BSTRW + nn;
                bh[nf][0] = Bh[r0]; bh[nf][1] = Bh[r1];
                bl[nf][0] = Bl[r0]; bl[nf][1] = Bl[r1];
            }
#pragma unroll
            for (int nf = 0; nf < 4; nf++)
#pragma unroll
                for (int mf = 0; mf < 2; mf++)
                    mma_bf16(acc[mf][nf], ah[mf][0],ah[mf][1],ah[mf][2],ah[mf][3], bh[nf][0], bh[nf][1]);
#pragma unroll
            for (int nf = 0; nf < 4; nf++)
#pragma unroll
                for (int mf = 0; mf < 2; mf++)
                    mma_bf16(acc[mf][nf], al[mf][0],al[mf][1],al[mf][2],al[mf][3], bh[nf][0], bh[nf][1]);
#pragma unroll
            for (int nf = 0; nf < 4; nf++)
#pragma unroll
                for (int mf = 0; mf < 2; mf++)
                    mma_bf16(acc[mf][nf], ah[mf][0],ah[mf][1],ah[mf][2],ah[mf][3], bl[nf][0], bl[nf][1]);
        }
    }

#pragma unroll
    for (int mf = 0; mf < 2; mf++) {
#pragma unroll
        for (int h = 0; h < 2; h++) {
            int r  = wm*32 + mf*16 + grp + h*8;
            int gr = m0 + r;
            if (gr < ne) {
                int slot   = g_slot[e*T_ + gr];
                float gate = g_gate[e*T_ + gr];
                float* yrow = g_Y + (size_t)slot * D_ + n0 + wn*32 + tig*2;
#pragma unroll
                for (int nf = 0; nf < 4; nf++) {
                    float o0 = acc[mf][nf][h*2+0] * gate;
                    float o1 = acc[mf][nf][h*2+1] * gate;
                    *(float2*)(yrow + nf*8) = make_float2(o0, o1);
                }
            }
        }
    }
}

// ---------------------------------------------------------------------------
// 4) combine the two assignment slots per token -> output
// ---------------------------------------------------------------------------
__global__ void combine_kernel(float* __restrict__ out) {
    int t = blockIdx.x;
    int d = threadIdx.x * 4;
    float4 a = *(const float4*)(g_Y + (size_t)(2*t)     * D_ + d);
    float4 b = *(const float4*)(g_Y + (size_t)(2*t + 1) * D_ + d);
    *(float4*)(out + (size_t)t * D_ + d) =
        make_float4(a.x + b.x, a.y + b.y, a.z + b.z, a.w + b.w);
}

// ---------------------------------------------------------------------------
// 5) losses + tokens_per_expert into the output tail
// ---------------------------------------------------------------------------
__global__ void finalize_kernel(float* __restrict__ out) {
    int tid = threadIdx.x;
    const float Tf = (float)T_;
    float* tail = out + (size_t)T_ * D_;
    if (tid < E_)
        tail[tid] = (float)g_count[tid] / (Tf * 2.f);
    if (tid == 0) {
        float z = g_zacc / Tf;
        float lb = 0.f;
#pragma unroll
        for (int e = 0; e < E_; e++)
            lb += (g_pacc[e] / Tf) * ((float)g_count[e] / (Tf * 2.f));
        lb *= (float)E_;
        float* s = tail + E_;
        s[0] = z;   s[1] = z * 0.001f;
        s[2] = lb;  s[3] = lb * 0.1f;
    }
}

// ---------------------------------------------------------------------------
// launch
// ---------------------------------------------------------------------------
extern "C" void kernel_launch(void* const* d_in, const int* in_sizes, int n_in,
                              void* d_out, int out_size) {
    (void)in_sizes; (void)n_in; (void)out_size;
    const float* x     = (const float*)d_in[0];
    const float* Wr    = (const float*)d_in[1];
    const float* Wup   = (const float*)d_in[2];
    const float* Wgate = (const float*)d_in[3];
    const float* Wdown = (const float*)d_in[4];
    float* out = (float*)d_out;

    init_kernel<<<1, 32>>>();
    router_kernel<<<T_ / 8, 256>>>(x, Wr);
    upgate_mma<<<dim3(F_/64, T_/128, E_), 256>>>(x, Wup, Wgate);
    down_mma  <<<dim3(D_/64, T_/128, E_), 256>>>(Wdown);
    combine_kernel<<<T_, 256>>>(out);
    finalize_kernel<<<1, 32>>>(out);
}